// round 9
// baseline (speedup 1.0000x reference)
#include <cuda_runtime.h>
#include <cuda_fp16.h>
#include <cstdint>

#define Bn 8
#define Cn 256
#define Hn 128
#define Wn 128
#define NE (Bn*Cn*Hn*Wn)

#define ROWB   128                  // gmem act row: 64 fp16 (hi32 | lo32)
#define ABLK   (130*ROWB)           // 16640 B per (b,y,g) block (rows 0,129 zero halo)
#define ACT_TOT ((size_t)Bn*Hn*8*ABLK)
#define WSTG   49152                // W bytes per (ocH,ky,g) stage
#define WCONV  (48ull*WSTG)
#define ASTG   (2*ABLK)             // 33280: two input-row blocks
#define STG    (ASTG + WSTG)        // 82432
#define DSMEM  (2*STG)              // 164864
#define DSMEM_REQ (DSMEM + 1024)
#define NT 512                      // threads per conv CTA

__device__ __align__(1024) unsigned char g_actA[ACT_TOT];
__device__ __align__(1024) unsigned char g_actB[ACT_TOT];
__device__ __align__(1024) unsigned char g_wpk[3*WCONV];
__device__ __align__(1024) unsigned char g_zero[ABLK];
__device__ float g_xm[NE];

// ---------------- helpers ----------------
static __device__ __forceinline__ uint32_t smem_u32(const void* p) {
    uint32_t r;
    asm("{ .reg .u64 t; cvta.to.shared.u64 t, %1; cvt.u32.u64 %0, t; }" : "=r"(r) : "l"(p));
    return r;
}
static __device__ __forceinline__ void cp16(uint32_t dst, const void* src) {
    asm volatile("cp.async.cg.shared.global [%0], [%1], 16;" :: "r"(dst), "l"(src) : "memory");
}
#define CP_COMMIT() asm volatile("cp.async.commit_group;" ::: "memory")
#define CP_WAIT1()  asm volatile("cp.async.wait_group 1;" ::: "memory")
#define CP_WAIT0()  asm volatile("cp.async.wait_group 0;" ::: "memory")

static __device__ __forceinline__ void ldm4(uint32_t a[4], uint32_t addr) {
    asm volatile("ldmatrix.sync.aligned.m8n8.x4.shared.b16 {%0,%1,%2,%3}, [%4];"
                 : "=r"(a[0]), "=r"(a[1]), "=r"(a[2]), "=r"(a[3]) : "r"(addr));
}
static __device__ __forceinline__ void mma16816(float d[4], const uint32_t a[4],
                                                uint32_t b0, uint32_t b1) {
    asm volatile("mma.sync.aligned.m16n8k16.row.col.f32.f16.f16.f32 "
                 "{%0,%1,%2,%3}, {%4,%5,%6,%7}, {%8,%9}, {%0,%1,%2,%3};"
                 : "+f"(d[0]), "+f"(d[1]), "+f"(d[2]), "+f"(d[3])
                 : "r"(a[0]), "r"(a[1]), "r"(a[2]), "r"(a[3]), "r"(b0), "r"(b1));
}
static __device__ __forceinline__ void split_f16(float a, unsigned short& hb, unsigned short& lb) {
    __half h = __float2half_rn(a);
    float hf = __half2float(h);
    __half l = __float2half_rn(a - hf);
    hb = __half_as_ushort(h);
    lb = __half_as_ushort(l);
}
static __device__ __forceinline__ void store_row(unsigned char* dst,
                                                 const uint32_t hv[16], const uint32_t lv[16]) {
    uint4* d4 = (uint4*)dst;
#pragma unroll
    for (int i = 0; i < 4; i++) {
        d4[i]     = make_uint4(hv[4*i], hv[4*i+1], hv[4*i+2], hv[4*i+3]);
        d4[i + 4] = make_uint4(lv[4*i], lv[4*i+1], lv[4*i+2], lv[4*i+3]);
    }
}

// ---------------- init: zero block + act halo rows ----------------
__global__ void k_zero() {
    int i = blockIdx.x * blockDim.x + threadIdx.x;
    const uint4 z = make_uint4(0, 0, 0, 0);
    if (i < 1040) { ((uint4*)g_zero)[i] = z; return; }
    int h = i - 1040;
    if (h >= 2 * 8192 * 2 * 8) return;
    int c = h & 7;   h >>= 3;
    int rsel = h & 1; h >>= 1;
    int blk = h & 8191; h >>= 13;
    unsigned char* buf = h ? g_actB : g_actA;
    *(uint4*)(buf + (size_t)blk * ABLK + (rsel ? 129 : 0) * ROWB + c * 16) = z;
}

// ---------------- weight pack ----------------
__global__ void k_packw(const float* __restrict__ w, unsigned char* __restrict__ dstB) {
    int u = blockIdx.x * blockDim.x + threadIdx.x;
    if (u >= 589824) return;
    int j    = u & 1;        int r = u >> 1;
    int lane = r & 31;       r >>= 5;
    int nt   = r & 15;       r >>= 4;
    int ks   = r & 3;        r >>= 2;
    int kx   = r % 3;        r /= 3;
    int g    = r & 7;        r >>= 3;
    int ky   = r % 3;        r /= 3;
    int ocH  = r;
    int oc = ocH * 128 + nt * 8 + (lane >> 2);
    int k  = ks * 16 + (lane & 3) * 2 + j * 8;
    int ci0 = g * 32 + (k & 31);
    float e0 = w[((oc * Cn + ci0) * 3 + ky) * 3 + kx];
    float e1 = w[((oc * Cn + ci0 + 1) * 3 + ky) * 3 + kx];
    unsigned short h0 = __half_as_ushort(__float2half_rn(e0));
    unsigned short h1 = __half_as_ushort(__float2half_rn(e1));
    ((uint32_t*)dstB)[u] = (uint32_t)h0 | ((uint32_t)h1 << 16);
}

// ---------------- prep: act0 = split(mask(prelu(x))) ----------------
__global__ void k_prep(const float* __restrict__ x, const float* __restrict__ pa) {
    extern __shared__ float sX[];
    const int y = blockIdx.x, b = blockIdx.y, tid = threadIdx.x;
    const float pav = pa[0];
    const float4* src = (const float4*)(x + ((size_t)b * Cn * Hn + y) * Wn);
    for (int i = tid; i < 8192; i += 256) {
        int ci = i >> 5, p4 = i & 31;
        ((float4*)sX)[ci * 32 + p4] = src[(size_t)ci * (Hn * Wn / 4) + p4];
    }
    __syncthreads();
#pragma unroll 1
    for (int k = 0; k < 4; k++) {
        int t = tid + k * 256;
        int px = t & 127, g = t >> 7;
        uint32_t hv[16], lv[16];
        unsigned short hprev = 0, lprev = 0;
#pragma unroll
        for (int j = 0; j < 32; j++) {
            float v = sX[(g * 32 + j) * 128 + px];
            float tt = v >= 0.f ? v : pav * v;
            float a = fabsf(tt) >= 0.1f ? tt : 0.f;
            unsigned short hb, lb;
            split_f16(a, hb, lb);
            if (j & 1) { hv[j >> 1] = (uint32_t)hprev | ((uint32_t)hb << 16);
                         lv[j >> 1] = (uint32_t)lprev | ((uint32_t)lb << 16); }
            else { hprev = hb; lprev = lb; }
        }
        store_row(g_actA + ((size_t)(b * Hn + y) * 8 + g) * ABLK + (px + 1) * ROWB, hv, lv);
    }
}

// ---------------- main conv: mma.sync implicit GEMM, 512 threads ----------------
// 8 M-warps x 2 N-warps; per warp: 32 px (mt=2) x 64 oc (nt=8)
template <int MODE>
__global__ __launch_bounds__(NT, 1)
void conv_mma(const unsigned char* __restrict__ actIn,
              const unsigned char* __restrict__ wcv,
              const float* __restrict__ bias,
              float* __restrict__ xm,
              const float* __restrict__ pa,
              unsigned char* __restrict__ actOut,
              float* __restrict__ out) {
    extern __shared__ __align__(16) unsigned char dsm_raw[];
    const uint32_t sb0 = smem_u32(dsm_raw);
    const uint32_t sb = (sb0 + 1023u) & ~1023u;
    unsigned char* dsm = dsm_raw + (sb - sb0);
    const int tid = threadIdx.x, lane = tid & 31, wid = tid >> 5;
    const int ocH = blockIdx.x, y = blockIdx.y * 2, b = blockIdx.z;
    const int mw = wid & 7;                 // M-warp 0..7 (32 rows each)
    const int ablk = mw >> 2;               // input-row block
    const int pxb = (mw & 3) * 32;          // px base within block
    const int ntB = (wid >> 3) * 8;         // N half

    float d[2][8][4];
#pragma unroll
    for (int mt = 0; mt < 2; mt++)
#pragma unroll
        for (int nt = 0; nt < 8; nt++)
#pragma unroll
            for (int q = 0; q < 4; q++) d[mt][nt][q] = 0.f;

    #define ISSUE(IT) do { \
        int s_ = (IT) & 1; \
        int ky_ = (IT) >> 3, g_ = (IT) & 7; \
        int ys0_ = y + ky_ - 1; \
        const unsigned char* a0 = ((unsigned)ys0_ < (unsigned)Hn) \
            ? actIn + ((size_t)(b * Hn + ys0_) * 8 + g_) * ABLK : g_zero; \
        const unsigned char* a1 = ((unsigned)(ys0_ + 1) < (unsigned)Hn) \
            ? actIn + ((size_t)(b * Hn + ys0_ + 1) * 8 + g_) * ABLK : g_zero; \
        const unsigned char* wSrc = wcv + (size_t)((ocH * 3 + ky_) * 8 + g_) * WSTG; \
        uint32_t ab = sb + s_ * STG; \
        for (int i = tid; i < 2080; i += NT) { \
            int bk = i >= 1040; int ii = i - bk * 1040; \
            int row = ii >> 3, c = ii & 7; \
            cp16(ab + bk * ABLK + row * ROWB + ((c ^ (row & 7)) << 4), \
                 (bk ? a1 : a0) + row * ROWB + c * 16); \
        } \
        uint32_t wb = ab + ASTG; \
        for (int i = tid; i < 3072; i += NT) \
            cp16(wb + i * 16, wSrc + (size_t)i * 16); \
        CP_COMMIT(); \
    } while (0)

    ISSUE(0);
    ISSUE(1);

    for (int it = 0; it < 24; it++) {
        const int s = it & 1;
        CP_WAIT1();
        __syncthreads();
        const uint32_t aB = sb + s * STG + ablk * ABLK;
        const unsigned char* wS = dsm + s * STG + ASTG;
#pragma unroll 1
        for (int ks = 0; ks < 4; ks++) {
#pragma unroll
            for (int kx = 0; kx < 3; kx++) {
                uint32_t aF[2][4];
#pragma unroll
                for (int mt = 0; mt < 2; mt++) {
                    int row = pxb + mt * 16 + (lane & 15) + kx;
                    int c = ks * 2 + (lane >> 4);
                    ldm4(aF[mt], aB + row * ROWB + ((c ^ (row & 7)) << 4));
                }
                const uint2* wrow = (const uint2*)(wS + ((size_t)(kx * 4 + ks) * 16 + ntB) * 256);
#pragma unroll
                for (int nt = 0; nt < 8; nt++) {
                    uint2 bf = wrow[nt * 32 + lane];
                    mma16816(d[0][nt], aF[0], bf.x, bf.y);
                    mma16816(d[1][nt], aF[1], bf.x, bf.y);
                }
            }
        }
        __syncthreads();
        if (it + 2 < 24) ISSUE(it + 2);
    }
    #undef ISSUE
    CP_WAIT0();
    __syncthreads();

    // ---- epilogue: fragments -> smem fp32 tile [m 256][oc 128] pitch 129 ----
    float* sD = (float*)dsm;
#pragma unroll
    for (int mt = 0; mt < 2; mt++) {
        int m0 = mw * 32 + mt * 16 + (lane >> 2);
        int n0base = ntB * 8 + (lane & 3) * 2;
#pragma unroll
        for (int nt = 0; nt < 8; nt++) {
            int n0 = n0base + nt * 8;
            sD[m0 * 129 + n0]           = d[mt][nt][0];
            sD[m0 * 129 + n0 + 1]       = d[mt][nt][1];
            sD[(m0 + 8) * 129 + n0]     = d[mt][nt][2];
            sD[(m0 + 8) * 129 + n0 + 1] = d[mt][nt][3];
        }
    }
    __syncthreads();

    const float pav = pa[0];
#pragma unroll 1
    for (int k = 0; k < 2; k++) {
        int t = tid + k * NT;
        int r = t & 255, gl = t >> 8;
        int px = r & 127, dy = r >> 7;
        int yout = y + dy;
        int oc0 = ocH * 128 + gl * 32;
        if (MODE == 1) {
            uint32_t hv[16], lv[16];
            unsigned short hprev = 0, lprev = 0;
#pragma unroll
            for (int j = 0; j < 32; j++) {
                float v = sD[r * 129 + gl * 32 + j] + bias[oc0 + j];
                size_t xi = ((size_t)(b * Cn + oc0 + j) * Hn + yout) * Wn + px;
                float m = fmaxf(xm[xi], v);
                xm[xi] = m;
                float tt = m >= 0.f ? m : pav * m;
                float a = fabsf(tt) >= 0.1f ? tt : 0.f;
                unsigned short hb, lb;
                split_f16(a, hb, lb);
                if (j & 1) { hv[j >> 1] = (uint32_t)hprev | ((uint32_t)hb << 16);
                             lv[j >> 1] = (uint32_t)lprev | ((uint32_t)lb << 16); }
                else { hprev = hb; lprev = lb; }
            }
            int gOut = ocH * 4 + gl;
            store_row(actOut + ((size_t)(b * Hn + yout) * 8 + gOut) * ABLK + (px + 1) * ROWB, hv, lv);
        } else {
#pragma unroll
            for (int j = 0; j < 32; j++) {
                float v = sD[r * 129 + gl * 32 + j] + bias[oc0 + j];
                out[((size_t)(b * Cn + oc0 + j) * Hn + yout) * Wn + px] = v;
            }
        }
    }
}

// ---------------- host ----------------
extern "C" void kernel_launch(void* const* d_in, const int* in_sizes, int n_in,
                              void* d_out, int out_size) {
    const float* x  = (const float*)d_in[0];
    const float* w1 = (const float*)d_in[1];
    const float* b1 = (const float*)d_in[2];
    const float* w2 = (const float*)d_in[3];
    const float* b2 = (const float*)d_in[4];
    const float* w3 = (const float*)d_in[5];
    const float* b3 = (const float*)d_in[6];
    const float* pa = (const float*)d_in[7];
    float* out = (float*)d_out;

    unsigned char *wpk, *actA, *actB;
    float* xm;
    cudaGetSymbolAddress((void**)&wpk,  g_wpk);
    cudaGetSymbolAddress((void**)&xm,   g_xm);
    cudaGetSymbolAddress((void**)&actA, g_actA);
    cudaGetSymbolAddress((void**)&actB, g_actB);

    cudaFuncSetAttribute(conv_mma<1>, cudaFuncAttributeMaxDynamicSharedMemorySize, DSMEM_REQ);
    cudaFuncSetAttribute(conv_mma<3>, cudaFuncAttributeMaxDynamicSharedMemorySize, DSMEM_REQ);
    cudaFuncSetAttribute(k_prep, cudaFuncAttributeMaxDynamicSharedMemorySize, 131072);

    k_zero<<<(1040 + 262144 + 255) / 256, 256>>>();
    k_packw<<<2304, 256>>>(w1, wpk);
    k_packw<<<2304, 256>>>(w2, wpk + WCONV);
    k_packw<<<2304, 256>>>(w3, wpk + 2 * WCONV);
    cudaMemcpyAsync(xm, x, (size_t)NE * 4, cudaMemcpyDeviceToDevice);
    k_prep<<<dim3(Hn, Bn), 256, 131072>>>(x, pa);

    dim3 grid(2, Hn / 2, Bn);
    conv_mma<1><<<grid, NT, DSMEM_REQ>>>(actA, wpk,             b1, xm, pa, actB, nullptr);
    conv_mma<1><<<grid, NT, DSMEM_REQ>>>(actB, wpk + WCONV,     b2, xm, pa, actA, nullptr);
    conv_mma<3><<<grid, NT, DSMEM_REQ>>>(actA, wpk + 2 * WCONV, b3, xm, pa, nullptr, out);
}

// round 10
// speedup vs baseline: 1.7029x; 1.7029x over previous
#include <cuda_runtime.h>
#include <cuda_fp16.h>
#include <cstdint>

#define Bn 8
#define Cn 256
#define Hn 128
#define Wn 128
#define NE (Bn*Cn*Hn*Wn)

// act block (b,y,g): 130 rows of 64B (fp16 x32ci), packed 2 rows per 128B line:
//   byte = L*128 + c*32 + par*16   (row = 2L+par, k-chunk c=0..3)
#define ABLK   8320                  // 65 lines * 128
#define ACT_TOT ((size_t)Bn*Hn*8*ABLK)
#define WSTG   24576                 // [kx3][ks2][nt16][lane32][j2] u32
#define WCONV  (48ull*WSTG)
#define ASTG   (2*ABLK)              // 16640
#define STG    (ASTG + WSTG)         // 41216
#define DSMEM  (2*STG)               // 82432
#define DSMEM_REQ (DSMEM + 1024)
#define NT 512

__device__ __align__(1024) unsigned char g_actA[ACT_TOT];
__device__ __align__(1024) unsigned char g_actB[ACT_TOT];
__device__ __align__(1024) unsigned char g_wpk[3*WCONV];
__device__ __align__(1024) unsigned char g_zero[ABLK];
__device__ float g_xm[NE];

// ---------------- helpers ----------------
static __device__ __forceinline__ uint32_t smem_u32(const void* p) {
    uint32_t r;
    asm("{ .reg .u64 t; cvta.to.shared.u64 t, %1; cvt.u32.u64 %0, t; }" : "=r"(r) : "l"(p));
    return r;
}
static __device__ __forceinline__ void cp16(uint32_t dst, const void* src) {
    asm volatile("cp.async.cg.shared.global [%0], [%1], 16;" :: "r"(dst), "l"(src) : "memory");
}
#define CP_COMMIT() asm volatile("cp.async.commit_group;" ::: "memory")
#define CP_WAIT1()  asm volatile("cp.async.wait_group 1;" ::: "memory")
#define CP_WAIT0()  asm volatile("cp.async.wait_group 0;" ::: "memory")

static __device__ __forceinline__ void ldm4(uint32_t a[4], uint32_t addr) {
    asm volatile("ldmatrix.sync.aligned.m8n8.x4.shared.b16 {%0,%1,%2,%3}, [%4];"
                 : "=r"(a[0]), "=r"(a[1]), "=r"(a[2]), "=r"(a[3]) : "r"(addr));
}
static __device__ __forceinline__ void mma16816(float d[4], const uint32_t a[4],
                                                uint32_t b0, uint32_t b1) {
    asm volatile("mma.sync.aligned.m16n8k16.row.col.f32.f16.f16.f32 "
                 "{%0,%1,%2,%3}, {%4,%5,%6,%7}, {%8,%9}, {%0,%1,%2,%3};"
                 : "+f"(d[0]), "+f"(d[1]), "+f"(d[2]), "+f"(d[3])
                 : "r"(a[0]), "r"(a[1]), "r"(a[2]), "r"(a[3]), "r"(b0), "r"(b1));
}
// store one 64B act row (row = 2L+par) into a block base (gmem, unswizzled)
static __device__ __forceinline__ void store_row64(unsigned char* blockbase, int row,
                                                   const uint32_t hv[16]) {
    unsigned char* base = blockbase + (row >> 1) * 128 + (row & 1) * 16;
#pragma unroll
    for (int c = 0; c < 4; c++)
        *(uint4*)(base + c * 32) = make_uint4(hv[4*c], hv[4*c+1], hv[4*c+2], hv[4*c+3]);
}

// ---------------- init: zero template block + act halo rows ----------------
__global__ void k_zero() {
    int i = blockIdx.x * blockDim.x + threadIdx.x;
    const uint4 z = make_uint4(0, 0, 0, 0);
    if (i < 520) { ((uint4*)g_zero)[i] = z; return; }
    int h = i - 520;
    if (h >= 2 * 8192 * 8) return;          // 2 bufs x 8192 blocks x 8 chunks
    int j = h & 7;  h >>= 3;
    int blk = h & 8191;
    unsigned char* buf = (h >> 13) ? g_actB : g_actA;
    unsigned char* bb = buf + (size_t)blk * ABLK;
    if (j < 4) *(uint4*)(bb + j * 32) = z;                     // row 0
    else       *(uint4*)(bb + 64 * 128 + (j - 4) * 32 + 16) = z; // row 129
}

// ---------------- weight pack: fragment order, single fp16 ----------------
// u32 idx = stage*6144 + ((q*16 + nt)*32 + lane)*2 + j ; stage = (ocH*3+ky)*8+g ; q = kx*2+ks
__global__ void k_packw(const float* __restrict__ w, unsigned char* __restrict__ dstB) {
    int u = blockIdx.x * blockDim.x + threadIdx.x;
    if (u >= 294912) return;
    int wI = u % 6144, stage = u / 6144;
    int g = stage & 7, kyH = stage >> 3;
    int ky = kyH % 3, ocH = kyH / 3;
    int j = wI & 1, lane = (wI >> 1) & 31, nt = (wI >> 6) & 15, q = wI >> 10;
    int ks = q & 1, kx = q >> 1;
    int oc = ocH * 128 + nt * 8 + (lane >> 2);
    int k  = ks * 16 + (lane & 3) * 2 + j * 8;     // 0..31
    int ci0 = g * 32 + k;
    float e0 = w[((oc * Cn + ci0) * 3 + ky) * 3 + kx];
    float e1 = w[((oc * Cn + ci0 + 1) * 3 + ky) * 3 + kx];
    unsigned short h0 = __half_as_ushort(__float2half_rn(e0));
    unsigned short h1 = __half_as_ushort(__float2half_rn(e1));
    ((uint32_t*)dstB)[u] = (uint32_t)h0 | ((uint32_t)h1 << 16);
}

// ---------------- prep: act0 = fp16(mask(prelu(x))) ----------------
__global__ void k_prep(const float* __restrict__ x, const float* __restrict__ pa) {
    extern __shared__ float sX[];
    const int y = blockIdx.x, b = blockIdx.y, tid = threadIdx.x;
    const float pav = pa[0];
    const float4* src = (const float4*)(x + ((size_t)b * Cn * Hn + y) * Wn);
    for (int i = tid; i < 8192; i += 256) {
        int ci = i >> 5, p4 = i & 31;
        ((float4*)sX)[ci * 32 + p4] = src[(size_t)ci * (Hn * Wn / 4) + p4];
    }
    __syncthreads();
#pragma unroll 1
    for (int k = 0; k < 4; k++) {
        int t = tid + k * 256;
        int px = t & 127, g = t >> 7;
        uint32_t hv[16];
        unsigned short hprev = 0;
#pragma unroll
        for (int j = 0; j < 32; j++) {
            float v = sX[(g * 32 + j) * 128 + px];
            float tt = v >= 0.f ? v : pav * v;
            float a = fabsf(tt) >= 0.1f ? tt : 0.f;
            unsigned short hb = __half_as_ushort(__float2half_rn(a));
            if (j & 1) hv[j >> 1] = (uint32_t)hprev | ((uint32_t)hb << 16);
            else hprev = hb;
        }
        store_row64(g_actA + ((size_t)(b * Hn + y) * 8 + g) * ABLK, px + 1, hv);
    }
}

// ---------------- main conv: mma.sync implicit GEMM, K=32/stage ----------------
// 512 thr: 8 M-warps (32 px) x 2 N-warps (64 oc); M=256 (2 rows), N=128
template <int MODE>
__global__ __launch_bounds__(NT, 1)
void conv_mma(const unsigned char* __restrict__ actIn,
              const unsigned char* __restrict__ wcv,
              const float* __restrict__ bias,
              float* __restrict__ xm,
              const float* __restrict__ pa,
              unsigned char* __restrict__ actOut,
              float* __restrict__ out) {
    extern __shared__ __align__(16) unsigned char dsm_raw[];
    const uint32_t sb0 = smem_u32(dsm_raw);
    const uint32_t sb = (sb0 + 1023u) & ~1023u;
    unsigned char* dsm = dsm_raw + (sb - sb0);
    const int tid = threadIdx.x, lane = tid & 31, wid = tid >> 5;
    const int ocH = blockIdx.x, y = blockIdx.y * 2, b = blockIdx.z;
    const int mw = wid & 7;
    const int ablk = mw >> 2;
    const int pxb = (mw & 3) * 32;
    const int ntB = (wid >> 3) * 8;

    float d[2][8][4];
#pragma unroll
    for (int mt = 0; mt < 2; mt++)
#pragma unroll
        for (int nt = 0; nt < 8; nt++)
#pragma unroll
            for (int q = 0; q < 4; q++) d[mt][nt][q] = 0.f;

    #define ISSUE(IT) do { \
        int s_ = (IT) & 1; \
        int ky_ = (IT) >> 3, g_ = (IT) & 7; \
        int ys0_ = y + ky_ - 1; \
        const unsigned char* a0 = ((unsigned)ys0_ < (unsigned)Hn) \
            ? actIn + ((size_t)(b * Hn + ys0_) * 8 + g_) * ABLK : g_zero; \
        const unsigned char* a1 = ((unsigned)(ys0_ + 1) < (unsigned)Hn) \
            ? actIn + ((size_t)(b * Hn + ys0_ + 1) * 8 + g_) * ABLK : g_zero; \
        const unsigned char* wSrc = wcv + (size_t)((ocH * 3 + ky_) * 8 + g_) * WSTG; \
        uint32_t ab = sb + s_ * STG; \
        for (int i = tid; i < 1040; i += NT) { \
            int bk = i >= 520; int ii = i - bk * 520; \
            int L = ii >> 3, cc = (ii >> 1) & 3, par = ii & 1; \
            cp16(ab + bk * ABLK + L * 128 + ((cc ^ (L & 3)) << 5) + (par << 4), \
                 (bk ? a1 : a0) + L * 128 + cc * 32 + par * 16); \
        } \
        uint32_t wb = ab + ASTG; \
        for (int i = tid; i < 1536; i += NT) \
            cp16(wb + i * 16, wSrc + (size_t)i * 16); \
        CP_COMMIT(); \
    } while (0)

    ISSUE(0);
    ISSUE(1);

    for (int it = 0; it < 24; it++) {
        const int s = it & 1;
        CP_WAIT1();
        __syncthreads();
        const uint32_t aB = sb + s * STG + ablk * ABLK;
        const unsigned char* wS = dsm + s * STG + ASTG;
#pragma unroll
        for (int ks = 0; ks < 2; ks++) {
#pragma unroll
            for (int kx = 0; kx < 3; kx++) {
                uint32_t aF[2][4];
#pragma unroll
                for (int mt = 0; mt < 2; mt++) {
                    int row = pxb + mt * 16 + (lane & 15) + kx;   // 0..129
                    int L = row >> 1, par = row & 1;
                    int c = ks * 2 + (lane >> 4);
                    ldm4(aF[mt], aB + L * 128 + ((c ^ (L & 3)) << 5) + (par << 4));
                }
                const uint2* wrow = (const uint2*)(wS + ((size_t)((kx * 2 + ks) * 16 + ntB)) * 256);
#pragma unroll
                for (int nt = 0; nt < 8; nt++) {
                    uint2 bf = wrow[nt * 32 + lane];
                    mma16816(d[0][nt], aF[0], bf.x, bf.y);
                    mma16816(d[1][nt], aF[1], bf.x, bf.y);
                }
            }
        }
        __syncthreads();
        if (it + 2 < 24) ISSUE(it + 2);
    }
    #undef ISSUE
    CP_WAIT0();

    // ---- epilogue: 2 passes of 128 M-rows through a smem fp32 tile ----
    float* sD = (float*)dsm;                       // 128 x 129 fp32 = 66048 B
    const float pav = pa[0];
#pragma unroll 1
    for (int p = 0; p < 2; p++) {
        __syncthreads();
        if ((mw >> 2) == p) {
#pragma unroll
            for (int mt = 0; mt < 2; mt++) {
                int m0 = (mw & 3) * 32 + mt * 16 + (lane >> 2);   // local row
                int n0base = ntB * 8 + (lane & 3) * 2;
#pragma unroll
                for (int nt = 0; nt < 8; nt++) {
                    int n0 = n0base + nt * 8;
                    sD[m0 * 129 + n0]           = d[mt][nt][0];
                    sD[m0 * 129 + n0 + 1]       = d[mt][nt][1];
                    sD[(m0 + 8) * 129 + n0]     = d[mt][nt][2];
                    sD[(m0 + 8) * 129 + n0 + 1] = d[mt][nt][3];
                }
            }
        }
        __syncthreads();
        const int px = tid & 127, gl = (tid >> 7) & 3;
        const int yout = y + p;
        const int oc0 = ocH * 128 + gl * 32;
        if (MODE == 1) {
            uint32_t hv[16];
            unsigned short hprev = 0;
#pragma unroll
            for (int j = 0; j < 32; j++) {
                float v = sD[px * 129 + gl * 32 + j] + bias[oc0 + j];
                size_t xi = ((size_t)(b * Cn + oc0 + j) * Hn + yout) * Wn + px;
                float m = fmaxf(xm[xi], v);
                xm[xi] = m;
                float tt = m >= 0.f ? m : pav * m;
                float a = fabsf(tt) >= 0.1f ? tt : 0.f;
                unsigned short hb = __half_as_ushort(__float2half_rn(a));
                if (j & 1) hv[j >> 1] = (uint32_t)hprev | ((uint32_t)hb << 16);
                else hprev = hb;
            }
            int gOut = ocH * 4 + gl;
            store_row64(actOut + ((size_t)(b * Hn + yout) * 8 + gOut) * ABLK, px + 1, hv);
        } else {
#pragma unroll
            for (int j = 0; j < 32; j++) {
                float v = sD[px * 129 + gl * 32 + j] + bias[oc0 + j];
                out[((size_t)(b * Cn + oc0 + j) * Hn + yout) * Wn + px] = v;
            }
        }
    }
}

// ---------------- host ----------------
extern "C" void kernel_launch(void* const* d_in, const int* in_sizes, int n_in,
                              void* d_out, int out_size) {
    const float* x  = (const float*)d_in[0];
    const float* w1 = (const float*)d_in[1];
    const float* b1 = (const float*)d_in[2];
    const float* w2 = (const float*)d_in[3];
    const float* b2 = (const float*)d_in[4];
    const float* w3 = (const float*)d_in[5];
    const float* b3 = (const float*)d_in[6];
    const float* pa = (const float*)d_in[7];
    float* out = (float*)d_out;

    unsigned char *wpk, *actA, *actB;
    float* xm;
    cudaGetSymbolAddress((void**)&wpk,  g_wpk);
    cudaGetSymbolAddress((void**)&xm,   g_xm);
    cudaGetSymbolAddress((void**)&actA, g_actA);
    cudaGetSymbolAddress((void**)&actB, g_actB);

    cudaFuncSetAttribute(conv_mma<1>, cudaFuncAttributeMaxDynamicSharedMemorySize, DSMEM_REQ);
    cudaFuncSetAttribute(conv_mma<3>, cudaFuncAttributeMaxDynamicSharedMemorySize, DSMEM_REQ);
    cudaFuncSetAttribute(k_prep, cudaFuncAttributeMaxDynamicSharedMemorySize, 131072);

    k_zero<<<(520 + 131072 + 255) / 256, 256>>>();
    k_packw<<<1152, 256>>>(w1, wpk);
    k_packw<<<1152, 256>>>(w2, wpk + WCONV);
    k_packw<<<1152, 256>>>(w3, wpk + 2 * WCONV);
    cudaMemcpyAsync(xm, x, (size_t)NE * 4, cudaMemcpyDeviceToDevice);
    k_prep<<<dim3(Hn, Bn), 256, 131072>>>(x, pa);

    dim3 grid(2, Hn / 2, Bn);
    conv_mma<1><<<grid, NT, DSMEM_REQ>>>(actA, wpk,             b1, xm, pa, actB, nullptr);
    conv_mma<1><<<grid, NT, DSMEM_REQ>>>(actB, wpk + WCONV,     b2, xm, pa, actA, nullptr);
    conv_mma<3><<<grid, NT, DSMEM_REQ>>>(actA, wpk + 2 * WCONV, b3, xm, pa, nullptr, out);
}